// round 1
// baseline (speedup 1.0000x reference)
#include <cuda_runtime.h>
#include <cstdint>

#define PP 3
#define CC 32
#define HH 256
#define WW 256
#define HW (HH * WW)

// Scratch: transposed features [P][H][W][C] (25 MB) + plane inverses + scale.
__device__ float g_tex[PP * HW * CC];
__device__ float g_inv[PP * 9];
__device__ float g_scale;

// ---------------------------------------------------------------------------
// Tiny prep: compute 3x3 plane inverses + coordinate scale (2 / box_warp).
// box_warp dtype is ambiguous (python int) -> decode int32 vs float32 bits.
// ---------------------------------------------------------------------------
__global__ void prep_kernel(const float* __restrict__ planes,
                            const int* __restrict__ bw_raw) {
    if (threadIdx.x == 0 && blockIdx.x == 0) {
        int bits = bw_raw[0];
        float bw;
        if (bits > 0 && bits < 1000000) bw = (float)bits;       // int32 payload
        else                            bw = __int_as_float(bits); // float payload
        g_scale = 2.0f / bw;

        for (int p = 0; p < PP; p++) {
            const float* a = planes + p * 9;
            float a00=a[0],a01=a[1],a02=a[2];
            float a10=a[3],a11=a[4],a12=a[5];
            float a20=a[6],a21=a[7],a22=a[8];
            float c00 =  (a11*a22 - a12*a21);
            float c01 = -(a10*a22 - a12*a20);
            float c02 =  (a10*a21 - a11*a20);
            float c10 = -(a01*a22 - a02*a21);
            float c11 =  (a00*a22 - a02*a20);
            float c12 = -(a00*a21 - a01*a20);
            float c20 =  (a01*a12 - a02*a11);
            float c21 = -(a00*a12 - a02*a10);
            float c22 =  (a00*a11 - a01*a10);
            float det = a00*c00 + a01*c01 + a02*c02;
            float id  = 1.0f / det;
            float* o = g_inv + p * 9;
            // inv[i][j] = cof[j][i] / det
            o[0]=c00*id; o[1]=c10*id; o[2]=c20*id;
            o[3]=c01*id; o[4]=c11*id; o[5]=c21*id;
            o[6]=c02*id; o[7]=c12*id; o[8]=c22*id;
        }
    }
}

// ---------------------------------------------------------------------------
// Layout transform: [P][C][H*W] -> [P][H*W][C] via 32x32 shared tile.
// Reads coalesced along HW, writes coalesced along C.
// ---------------------------------------------------------------------------
__global__ void transpose_kernel(const float* __restrict__ in) {
    __shared__ float tile[32][33];
    int p  = blockIdx.y;
    int ib = blockIdx.x * 32;          // HW tile base
    int tx = threadIdx.x, ty = threadIdx.y;
    // read in[p][c=ty][i=ib+tx]   (tx contiguous -> coalesced)
    tile[ty][tx] = in[(size_t)(p * CC + ty) * HW + ib + tx];
    __syncthreads();
    // write g_tex[p][i=ib+ty][c=tx]  (tx contiguous -> coalesced)
    g_tex[(size_t)p * HW * CC + (size_t)(ib + ty) * CC + tx] = tile[tx][ty];
}

// ---------------------------------------------------------------------------
// Sampler: one thread = one (plane, point, 4 channels).
// 8 threads per point; each bilinear corner is a contiguous 128B line, so each
// corner load per warp-octet is a single fully-used L2 transaction.
// ---------------------------------------------------------------------------
__global__ void __launch_bounds__(256) sample_kernel(
    const float* __restrict__ coords, float* __restrict__ out, int M) {
    int t  = blockIdx.x * blockDim.x + threadIdx.x;
    int pm = t >> 3;
    if (pm >= PP * M) return;
    int cq = t & 7;                    // float4 group within the 32 channels
    int p  = pm / M;
    int m  = pm - p * M;

    float s = g_scale;
    const float* cp = coords + 3 * m;
    float x = __ldg(cp)     * s;
    float y = __ldg(cp + 1) * s;
    float z = __ldg(cp + 2) * s;

    const float* inv = g_inv + p * 9;
    float u = x * inv[0] + y * inv[3] + z * inv[6];
    float v = x * inv[1] + y * inv[4] + z * inv[7];

    float ix = (u + 1.0f) * (0.5f * (WW - 1));
    float iy = (v + 1.0f) * (0.5f * (HH - 1));
    float fx = floorf(ix), fy = floorf(iy);

    // weights exactly per reference ordering: (ix_se - ix), (ix - ix_nw), ...
    float wxe = ix - fx;
    float wxw = (fx + 1.0f) - ix;
    float wys = iy - fy;
    float wyn = (fy + 1.0f) - iy;
    float w_nw = wxw * wyn;
    float w_ne = wxe * wyn;
    float w_sw = wxw * wys;
    float w_se = wxe * wys;

    int x0 = min(max((int)fx,     0), WW - 1);
    int y0 = min(max((int)fy,     0), HH - 1);
    int x1 = min(max((int)fx + 1, 0), WW - 1);
    int y1 = min(max((int)fy + 1, 0), HH - 1);

    const float4* tex = (const float4*)(g_tex + (size_t)p * HW * CC);
    float4 v00 = __ldg(tex + (size_t)(y0 * WW + x0) * 8 + cq);
    float4 v01 = __ldg(tex + (size_t)(y0 * WW + x1) * 8 + cq);
    float4 v10 = __ldg(tex + (size_t)(y1 * WW + x0) * 8 + cq);
    float4 v11 = __ldg(tex + (size_t)(y1 * WW + x1) * 8 + cq);

    float4 r;
    r.x = w_nw*v00.x + w_ne*v01.x + w_sw*v10.x + w_se*v11.x;
    r.y = w_nw*v00.y + w_ne*v01.y + w_sw*v10.y + w_se*v11.y;
    r.z = w_nw*v00.z + w_ne*v01.z + w_sw*v10.z + w_se*v11.z;
    r.w = w_nw*v00.w + w_ne*v01.w + w_sw*v10.w + w_se*v11.w;

    ((float4*)out)[(size_t)pm * 8 + cq] = r;
}

// ---------------------------------------------------------------------------
extern "C" void kernel_launch(void* const* d_in, const int* in_sizes, int n_in,
                              void* d_out, int out_size) {
    const float* feats  = (const float*)d_in[0];   // [1,3,32,256,256] fp32
    const float* coords = (const float*)d_in[1];   // [1,M,3] fp32
    const float* planes = (const float*)d_in[2];   // [3,3,3] fp32
    const int*   bw     = (const int*)d_in[3];     // scalar box_warp

    int M = in_sizes[1] / 3;

    prep_kernel<<<1, 32>>>(planes, bw);

    dim3 tb(32, 32);
    dim3 tg(HW / 32, PP);
    transpose_kernel<<<tg, tb>>>(feats);

    long long total = (long long)PP * M * 8;
    int blocks = (int)((total + 255) / 256);
    sample_kernel<<<blocks, 256>>>(coords, (float*)d_out, M);
}

// round 2
// speedup vs baseline: 1.0509x; 1.0509x over previous
#include <cuda_runtime.h>
#include <cuda_fp16.h>
#include <cstdint>

#define PP 3
#define CC 32
#define HH 256
#define WW 256
#define HW (HH * WW)

// Scratch: transposed fp16 features [P][H][W][C] (12.6 MB) + plane inverses + scale.
__device__ __half g_tex[PP * HW * CC];
__device__ float  g_inv[PP * 9];
__device__ float  g_scale;

// ---------------------------------------------------------------------------
// Layout transform: [P][C][H*W] fp32 -> [P][H*W][C] fp16 via 32x32 shared tile.
// Reads coalesced along HW, writes coalesced along C.
// Block (0,0) thread 0 additionally computes the 3x3 plane inverses + scale
// (folds the former prep_kernel launch away).
// ---------------------------------------------------------------------------
__global__ void transpose_kernel(const float* __restrict__ in,
                                 const float* __restrict__ planes,
                                 const int* __restrict__ bw_raw) {
    if (blockIdx.x == 0 && blockIdx.y == 0 &&
        threadIdx.x == 0 && threadIdx.y == 0) {
        int bits = bw_raw[0];
        float bw;
        if (bits > 0 && bits < 1000000) bw = (float)bits;          // int payload
        else                            bw = __int_as_float(bits); // float payload
        g_scale = 2.0f / bw;

        for (int p = 0; p < PP; p++) {
            const float* a = planes + p * 9;
            float a00=a[0],a01=a[1],a02=a[2];
            float a10=a[3],a11=a[4],a12=a[5];
            float a20=a[6],a21=a[7],a22=a[8];
            float c00 =  (a11*a22 - a12*a21);
            float c01 = -(a10*a22 - a12*a20);
            float c02 =  (a10*a21 - a11*a20);
            float c10 = -(a01*a22 - a02*a21);
            float c11 =  (a00*a22 - a02*a20);
            float c12 = -(a00*a21 - a01*a20);
            float c20 =  (a01*a12 - a02*a11);
            float c21 = -(a00*a12 - a02*a10);
            float c22 =  (a00*a11 - a01*a10);
            float det = a00*c00 + a01*c01 + a02*c02;
            float id  = 1.0f / det;
            float* o = g_inv + p * 9;
            o[0]=c00*id; o[1]=c10*id; o[2]=c20*id;
            o[3]=c01*id; o[4]=c11*id; o[5]=c21*id;
            o[6]=c02*id; o[7]=c12*id; o[8]=c22*id;
        }
    }

    __shared__ float tile[32][33];
    int p  = blockIdx.y;
    int ib = blockIdx.x * 32;          // HW tile base
    int tx = threadIdx.x, ty = threadIdx.y;
    // read in[p][c=ty][i=ib+tx]   (tx contiguous -> coalesced)
    tile[ty][tx] = in[(size_t)(p * CC + ty) * HW + ib + tx];
    __syncthreads();
    // write g_tex[p][i=ib+ty][c=tx]  (tx contiguous -> coalesced)
    g_tex[(size_t)p * HW * CC + (size_t)(ib + ty) * CC + tx] =
        __float2half_rn(tile[tx][ty]);
}

// ---------------------------------------------------------------------------
// Sampler: one thread = one (plane, point, 8 fp16 channels = 16B load).
// 4 threads per point; each bilinear corner is a contiguous 64B chunk, fully
// used (2 full 32B sectors) regardless of random point order.
// ---------------------------------------------------------------------------
__device__ __forceinline__ float2 h2f(unsigned u) {
    return __half22float2(*reinterpret_cast<__half2*>(&u));
}

__device__ __forceinline__ void acc_corner(uint4 q, float w, float* a) {
    float2 f;
    f = h2f(q.x); a[0] += w * f.x; a[1] += w * f.y;
    f = h2f(q.y); a[2] += w * f.x; a[3] += w * f.y;
    f = h2f(q.z); a[4] += w * f.x; a[5] += w * f.y;
    f = h2f(q.w); a[6] += w * f.x; a[7] += w * f.y;
}

__global__ void __launch_bounds__(256) sample_kernel(
    const float* __restrict__ coords, float* __restrict__ out, int M) {
    int t  = blockIdx.x * blockDim.x + threadIdx.x;
    int pm = t >> 2;
    if (pm >= PP * M) return;
    int cq = t & 3;                    // 8-channel group within the 32 channels
    int p  = pm / M;
    int m  = pm - p * M;

    float s = g_scale;
    const float* cp = coords + 3 * m;
    float x = __ldg(cp)     * s;
    float y = __ldg(cp + 1) * s;
    float z = __ldg(cp + 2) * s;

    const float* inv = g_inv + p * 9;
    float u = x * inv[0] + y * inv[3] + z * inv[6];
    float v = x * inv[1] + y * inv[4] + z * inv[7];

    float ix = (u + 1.0f) * (0.5f * (WW - 1));
    float iy = (v + 1.0f) * (0.5f * (HH - 1));
    float fx = floorf(ix), fy = floorf(iy);

    // weights exactly per reference ordering
    float wxe = ix - fx;
    float wxw = (fx + 1.0f) - ix;
    float wys = iy - fy;
    float wyn = (fy + 1.0f) - iy;
    float w_nw = wxw * wyn;
    float w_ne = wxe * wyn;
    float w_sw = wxw * wys;
    float w_se = wxe * wys;

    int x0 = min(max((int)fx,     0), WW - 1);
    int y0 = min(max((int)fy,     0), HH - 1);
    int x1 = min(max((int)fx + 1, 0), WW - 1);
    int y1 = min(max((int)fy + 1, 0), HH - 1);

    // texture as uint4 (16B = 8 halves); one point = 4 uint4 (64B)
    const uint4* tex = (const uint4*)(g_tex + (size_t)p * HW * CC);
    uint4 q00 = __ldg(tex + (size_t)(y0 * WW + x0) * 4 + cq);
    uint4 q01 = __ldg(tex + (size_t)(y0 * WW + x1) * 4 + cq);
    uint4 q10 = __ldg(tex + (size_t)(y1 * WW + x0) * 4 + cq);
    uint4 q11 = __ldg(tex + (size_t)(y1 * WW + x1) * 4 + cq);

    float a[8] = {0.f, 0.f, 0.f, 0.f, 0.f, 0.f, 0.f, 0.f};
    acc_corner(q00, w_nw, a);
    acc_corner(q01, w_ne, a);
    acc_corner(q10, w_sw, a);
    acc_corner(q11, w_se, a);

    // output: fp32, 8 channels = two float4 stores, fully coalesced per warp
    float4* o = (float4*)out + (size_t)pm * 8 + cq * 2;
    o[0] = make_float4(a[0], a[1], a[2], a[3]);
    o[1] = make_float4(a[4], a[5], a[6], a[7]);
}

// ---------------------------------------------------------------------------
extern "C" void kernel_launch(void* const* d_in, const int* in_sizes, int n_in,
                              void* d_out, int out_size) {
    const float* feats  = (const float*)d_in[0];   // [1,3,32,256,256] fp32
    const float* coords = (const float*)d_in[1];   // [1,M,3] fp32
    const float* planes = (const float*)d_in[2];   // [3,3,3] fp32
    const int*   bw     = (const int*)d_in[3];     // scalar box_warp

    int M = in_sizes[1] / 3;

    dim3 tb(32, 32);
    dim3 tg(HW / 32, PP);
    transpose_kernel<<<tg, tb>>>(feats, planes, bw);

    long long total = (long long)PP * M * 4;
    int blocks = (int)((total + 255) / 256);
    sample_kernel<<<blocks, 256>>>(coords, (float*)d_out, M);
}

// round 3
// speedup vs baseline: 1.3119x; 1.2483x over previous
#include <cuda_runtime.h>
#include <cuda_fp16.h>
#include <cstdint>

#define PP 3
#define CC 32
#define HH 256
#define WW 256
#define HW (HH * WW)

// Scratch: transposed fp16 features [P][H][W][C] (12.6 MB) + plane inverses + scale.
__device__ __half g_tex[PP * HW * CC];
__device__ float  g_inv[PP * 9];
__device__ float  g_scale;

// ---------------------------------------------------------------------------
// Layout transform: [P][C][HW] fp32 -> [P][HW][C] fp16.
// 256 threads/block, 64 HW positions per block.
// Phase 1: float4 coalesced reads into a padded smem tile.
// Phase 2: half2 writes, each warp emits full 128B lines.
// Block (0,0) thread 0 also computes plane inverses + scale (prep folded in).
// ---------------------------------------------------------------------------
__global__ void __launch_bounds__(256) transpose_kernel(
    const float* __restrict__ in,
    const float* __restrict__ planes,
    const int* __restrict__ bw_raw) {
    if (blockIdx.x == 0 && blockIdx.y == 0 && threadIdx.x == 0) {
        int bits = bw_raw[0];
        float bw;
        if (bits > 0 && bits < 1000000) bw = (float)bits;          // int payload
        else                            bw = __int_as_float(bits); // float payload
        g_scale = 2.0f / bw;

        for (int p = 0; p < PP; p++) {
            const float* a = planes + p * 9;
            float a00=a[0],a01=a[1],a02=a[2];
            float a10=a[3],a11=a[4],a12=a[5];
            float a20=a[6],a21=a[7],a22=a[8];
            float c00 =  (a11*a22 - a12*a21);
            float c01 = -(a10*a22 - a12*a20);
            float c02 =  (a10*a21 - a11*a20);
            float c10 = -(a01*a22 - a02*a21);
            float c11 =  (a00*a22 - a02*a20);
            float c12 = -(a00*a21 - a01*a20);
            float c20 =  (a01*a12 - a02*a11);
            float c21 = -(a00*a12 - a02*a10);
            float c22 =  (a00*a11 - a01*a10);
            float det = a00*c00 + a01*c01 + a02*c02;
            float id  = 1.0f / det;
            float* o = g_inv + p * 9;
            o[0]=c00*id; o[1]=c10*id; o[2]=c20*id;
            o[3]=c01*id; o[4]=c11*id; o[5]=c21*id;
            o[6]=c02*id; o[7]=c12*id; o[8]=c22*id;
        }
    }

    __shared__ float tile[CC][65];       // 64 HW + 1 pad
    int p   = blockIdx.y;
    int ib  = blockIdx.x * 64;           // HW tile base
    int tid = threadIdx.x;

    // Phase 1: read 32ch x 64hw as float4
    const float4* in4 = (const float4*)in + (size_t)p * CC * (HW / 4);
    int f = tid & 15;                    // float4 index within 64 hw
    int c = tid >> 4;                    // channel 0..15
    #pragma unroll
    for (int r = 0; r < 2; r++) {
        int cc = c + r * 16;
        float4 v = __ldg(in4 + (size_t)cc * (HW / 4) + (ib >> 2) + f);
        tile[cc][4*f + 0] = v.x;
        tile[cc][4*f + 1] = v.y;
        tile[cc][4*f + 2] = v.z;
        tile[cc][4*f + 3] = v.w;
    }
    __syncthreads();

    // Phase 2: write [hw][ch] as half2; warp covers 2 hw positions = 128B
    int cp = tid & 15;                   // channel pair 0..15
    int i0 = tid >> 4;                   // hw 0..15
    __half2* dst = (__half2*)(g_tex + (size_t)p * HW * CC);
    #pragma unroll
    for (int r = 0; r < 4; r++) {
        int i = i0 + r * 16;
        __half2 h = __floats2half2_rn(tile[2*cp][i], tile[2*cp + 1][i]);
        dst[(size_t)(ib + i) * (CC/2) + cp] = h;
    }
}

// ---------------------------------------------------------------------------
// Sampler: 8 lanes per (plane, point).
// Each bilinear row-pair (x0,x1 adjacent) is 128B contiguous -> one LDG.128
// across the 8 lanes (lanes 0-3 = west texel, 4-7 = east texel).
// Each lane applies its corner's folded weights, then a single shfl_xor(4)
// reduce combines west+east. One STG.128 per lane; warp output is 512B dense.
// ---------------------------------------------------------------------------
__device__ __forceinline__ float2 h2f(unsigned u) {
    return __half22float2(*reinterpret_cast<__half2*>(&u));
}

__global__ void __launch_bounds__(256) sample_kernel(
    const float* __restrict__ coords, float* __restrict__ out, int M) {
    int t  = blockIdx.x * blockDim.x + threadIdx.x;
    int pm = t >> 3;
    int q  = t & 7;
    int PPM = PP * M;
    if (pm >= PPM) return;

    int p = (pm >= 2*M) ? 2 : (pm >= M ? 1 : 0);
    int m = pm - p * M;

    float s = g_scale;
    const float* cp2 = coords + 3 * m;
    float x = __ldg(cp2)     * s;
    float y = __ldg(cp2 + 1) * s;
    float z = __ldg(cp2 + 2) * s;

    const float* inv = g_inv + p * 9;
    float u = x * inv[0] + y * inv[3] + z * inv[6];
    float v = x * inv[1] + y * inv[4] + z * inv[7];

    float ix = (u + 1.0f) * (0.5f * (WW - 1));
    float iy = (v + 1.0f) * (0.5f * (HH - 1));
    float fx = floorf(ix), fy = floorf(iy);

    float wxe = ix - fx;
    float wxw = (fx + 1.0f) - ix;
    float wys = iy - fy;
    float wyn = (fy + 1.0f) - iy;

    int fxi = (int)fx;
    int fyi = (int)fy;
    // x clamp folded onto the in-bounds adjacent pair
    if (fxi > WW - 2) { wxe = wxw + wxe; wxw = 0.0f; }
    if (fxi < 0)      { wxw = wxw + wxe; wxe = 0.0f; }
    int bx = min(max(fxi, 0), WW - 2);
    int y0 = min(max(fyi,     0), HH - 1);
    int y1 = min(max(fyi + 1, 0), HH - 1);

    // this lane's corner weight (west for q<4, east for q>=4), folded with rows
    float wown = (q & 4) ? wxe : wxw;
    float c0 = wyn * wown;   // row y0
    float c1 = wys * wown;   // row y1

    const uint4* tex = (const uint4*)g_tex + (size_t)p * (HW * 4);
    uint4 r0 = __ldg(tex + (size_t)(y0 * WW + bx) * 4 + q);
    uint4 r1 = __ldg(tex + (size_t)(y1 * WW + bx) * 4 + q);

    float a[8];
    float2 f0, f1;
    f0 = h2f(r0.x); f1 = h2f(r1.x);
    a[0] = c0*f0.x + c1*f1.x;  a[1] = c0*f0.y + c1*f1.y;
    f0 = h2f(r0.y); f1 = h2f(r1.y);
    a[2] = c0*f0.x + c1*f1.x;  a[3] = c0*f0.y + c1*f1.y;
    f0 = h2f(r0.z); f1 = h2f(r1.z);
    a[4] = c0*f0.x + c1*f1.x;  a[5] = c0*f0.y + c1*f1.y;
    f0 = h2f(r0.w); f1 = h2f(r1.w);
    a[6] = c0*f0.x + c1*f1.x;  a[7] = c0*f0.y + c1*f1.y;

    // combine west+east corners (lane q <-> q^4 hold the same channel slice)
    #pragma unroll
    for (int k = 0; k < 8; k++)
        a[k] += __shfl_xor_sync(0xffffffffu, a[k], 4);

    // store: lanes 0-3 write a[0..3] at ch 8q, lanes 4-7 write a[4..7] at ch 8(q-4)+4
    float* ob = out + (size_t)pm * CC;
    int qq = q & 3;
    float4 st = (q & 4) ? make_float4(a[4], a[5], a[6], a[7])
                        : make_float4(a[0], a[1], a[2], a[3]);
    ((float4*)ob)[(q & 4) ? (2*qq + 1) : (2*qq)] = st;
}

// ---------------------------------------------------------------------------
extern "C" void kernel_launch(void* const* d_in, const int* in_sizes, int n_in,
                              void* d_out, int out_size) {
    const float* feats  = (const float*)d_in[0];   // [1,3,32,256,256] fp32
    const float* coords = (const float*)d_in[1];   // [1,M,3] fp32
    const float* planes = (const float*)d_in[2];   // [3,3,3] fp32
    const int*   bw     = (const int*)d_in[3];     // scalar box_warp

    int M = in_sizes[1] / 3;

    dim3 tg(HW / 64, PP);
    transpose_kernel<<<tg, 256>>>(feats, planes, bw);

    long long total = (long long)PP * M * 8;
    int blocks = (int)((total + 255) / 256);
    sample_kernel<<<blocks, 256>>>(coords, (float*)d_out, M);
}